// round 7
// baseline (speedup 1.0000x reference)
#include <cuda_runtime.h>
#include <math.h>

#define PI_F 3.14159265358979323846f

// Precomputed circuit data (setup_kernel -> qc_kernel)
// Columns are PRE-ROTATED: odd-parity columns multiplied by (-i), so the
// per-sample matvec is a uniform packed-f32x2 FMA.
__device__ float2 g_Uq[16][16];   // [col j][row i]
__device__ float2 g_Uv[16][16];
__device__ float  g_kx[4];        // <X_w> of the fixed k-register state

// ---------- helpers ----------
__device__ __forceinline__ float2 cmul(float2 a, float2 b){
    return make_float2(a.x*b.x - a.y*b.y, a.x*b.y + a.y*b.x);
}
__device__ __forceinline__ float2 cadd(float2 a, float2 b){ return make_float2(a.x+b.x, a.y+b.y); }
__device__ __forceinline__ float2 expi(float a){ float s,c; __sincosf(a,&s,&c); return make_float2(c,s); }
__device__ __forceinline__ float2 cscale(float2 a, float s){ return make_float2(a.x*s, a.y*s); }
__device__ __forceinline__ float2 shflx(float2 v, int m){
    return make_float2(__shfl_xor_sync(0xffffffffu, v.x, m),
                       __shfl_xor_sync(0xffffffffu, v.y, m));
}
__device__ __forceinline__ float fast_tanh(float x){
    float e = __expf(2.f * x);
    return 1.f - 2.f / (e + 1.f);
}
// packed f32x2
__device__ __forceinline__ unsigned long long pk2(float x, float y){
    unsigned long long r; asm("mov.b64 %0, {%1,%2};" : "=l"(r) : "f"(x), "f"(y)); return r;
}
__device__ __forceinline__ float2 upk2(unsigned long long a){
    float2 r; asm("mov.b64 {%0,%1}, %2;" : "=f"(r.x), "=f"(r.y) : "l"(a)); return r;
}
__device__ __forceinline__ unsigned long long fma2(unsigned long long a, unsigned long long b,
                                                   unsigned long long c){
    unsigned long long d;
    asm("fma.rn.f32x2 %0, %1, %2, %3;" : "=l"(d) : "l"(a), "l"(b), "l"(c));
    return d;
}

// fully-unrolled 8-gate initQKV circuit on 16 amplitudes across a 16-lane group
__device__ __forceinline__ float2 sim16(const float* __restrict__ rot,
                                        const float* __restrict__ crx,
                                        int col, int lane)
{
    float2 s = (lane == col) ? make_float2(1.f, 0.f) : make_float2(0.f, 0.f);
    #pragma unroll
    for (int g = 0; g < 8; g++){
        const int pa_[8] = {0,1,2,3,0,1,2,3};
        const int pb_[8] = {1,2,3,0,3,0,1,2};
        const int ma = 8 >> pa_[g], mb = 8 >> pb_[g];

        float phi = rot[3*g], th = rot[3*g+1], om = rot[3*g+2];
        float c, sn; __sincosf(0.5f*th, &sn, &c);
        float2 u00 = cscale(expi(-0.5f*(phi+om)),  c);
        float2 u01 = cscale(expi( 0.5f*(phi-om)), -sn);
        float2 u10 = cscale(expi(-0.5f*(phi-om)),  sn);
        float2 u11 = cscale(expi( 0.5f*(phi+om)),  c);
        float2 o = shflx(s, ma);
        s = (lane & ma) ? cadd(cmul(u10, o), cmul(u11, s))
                        : cadd(cmul(u00, s), cmul(u01, o));

        float cc, ss; __sincosf(0.5f*crx[g], &ss, &cc);
        o = shflx(s, mb);
        if (lane & ma) s = make_float2(cc*s.x + ss*o.y, cc*s.y - ss*o.x);

        o = shflx(s, mb);
        if (lane & ma) s = o;
    }
    return s;
}

// 17 blocks x 32 threads: block b handles chains 2b and 2b+1 (one per 16-lane half).
// Chains 0-15: U_q columns; 16-31: U_v columns; 32,33: k circuit (both halves identical).
__global__ void __launch_bounds__(32)
setup_kernel(const float* __restrict__ qr, const float* __restrict__ kr,
             const float* __restrict__ vr, const float* __restrict__ qc,
             const float* __restrict__ kc, const float* __restrict__ vc)
{
    int grp  = blockIdx.x * 2 + (threadIdx.x >> 4);   // 0..33
    int lane = threadIdx.x & 15;

    const float* rot; const float* crx; int col;
    if (grp < 16)      { rot = qr; crx = qc; col = grp;      }
    else if (grp < 32) { rot = vr; crx = vc; col = grp - 16; }
    else               { rot = kr; crx = kc; col = 0;        }

    float2 s = sim16(rot, crx, col, lane);

    if (grp < 32){
        // pre-rotate odd-parity columns by (-i): (x,y) -> (y,-x)
        if (__popc(col) & 1) s = make_float2(s.y, -s.x);
        if (grp < 16) g_Uq[col][lane] = s;
        else          g_Uv[col][lane] = s;
    } else {
        // <X_w> of k state; shfl masks <=8 stay within each 16-lane half
        #pragma unroll
        for (int w = 0; w < 4; w++){
            int m = 8 >> w;
            float2 o = shflx(s, m);
            float v = s.x*o.x + s.y*o.y;
            v += __shfl_xor_sync(0xffffffffu, v, 1);
            v += __shfl_xor_sync(0xffffffffu, v, 2);
            v += __shfl_xor_sync(0xffffffffu, v, 4);
            v += __shfl_xor_sync(0xffffffffu, v, 8);
            if (grp == 32 && lane == 0) g_kx[w] = v;
        }
    }
}

// 256 threads = 64 samples (4 lanes each). grid = B/64.
__global__ void __launch_bounds__(256, 4)
qc_kernel(const float* __restrict__ x1, const float* __restrict__ pre_w,
          const float* __restrict__ pre_b,
          const float* __restrict__ ln_w, const float* __restrict__ ln_b,
          const float* __restrict__ head_w, const float* __restrict__ head_b,
          float* __restrict__ out, int B)
{
    __shared__ float4 sUq[128];   // 16x16 complex, pre-rotated columns
    __shared__ float4 sUv[128];
    __shared__ float  sW[384];    // pre_w [4][96]
    __shared__ float  sKx[4];
    __shared__ float  sPB[4];
    __shared__ float  sLnW[8], sLnB[8], sHW[16], sHB[2];

    int t = threadIdx.x;

    if (t < 128){
        sUq[t] = ((const float4*)g_Uq)[t];
        sUv[t] = ((const float4*)g_Uv)[t];
    }
    for (int i = t; i < 384; i += 256) sW[i] = pre_w[i];
    if (t < 4)              { sPB[t] = pre_b[t]; sKx[t] = g_kx[t]; }
    if (t >= 4 && t < 12)   sLnW[t-4]  = ln_w[t-4];
    if (t >= 12 && t < 20)  sLnB[t-12] = ln_b[t-12];
    if (t >= 20 && t < 36)  sHW[t-20]  = head_w[t-20];
    if (t >= 36 && t < 38)  sHB[t-36]  = head_b[t-36];
    __syncthreads();

    int s_idx = blockIdx.x * 64 + (t >> 2);
    int l     = t & 3;                       // quad lane: rows 4l..4l+3
    if (s_idx >= B) return;

    const float4* sW4 = (const float4*)sW;

    // ---- x = x1[s] @ pre_w.T + pre_b (24 of 96 per lane, butterfly reduce) ----
    float a0 = 0.f, a1 = 0.f, a2 = 0.f, a3 = 0.f;
    {
        const float4* row = (const float4*)(x1 + (size_t)s_idx * 96) + l * 6;
        #pragma unroll
        for (int k = 0; k < 6; k++){
            float4 v = row[k];
            float4 w0 = sW4[      l*6 + k];
            float4 w1 = sW4[ 24 + l*6 + k];
            float4 w2 = sW4[ 48 + l*6 + k];
            float4 w3 = sW4[ 72 + l*6 + k];
            a0 += v.x*w0.x + v.y*w0.y + v.z*w0.z + v.w*w0.w;
            a1 += v.x*w1.x + v.y*w1.y + v.z*w1.z + v.w*w1.w;
            a2 += v.x*w2.x + v.y*w2.y + v.z*w2.z + v.w*w2.w;
            a3 += v.x*w3.x + v.y*w3.y + v.z*w3.z + v.w*w3.w;
        }
        #pragma unroll
        for (int d = 1; d <= 2; d <<= 1){
            a0 += __shfl_xor_sync(0xffffffffu, a0, d);
            a1 += __shfl_xor_sync(0xffffffffu, a1, d);
            a2 += __shfl_xor_sync(0xffffffffu, a2, d);
            a3 += __shfl_xor_sync(0xffffffffu, a3, d);
        }
    }
    float xw[4] = { a0 + sPB[0], a1 + sPB[1], a2 + sPB[2], a3 + sPB[3] };

    float hc[4], hs[4];
    #pragma unroll
    for (int w = 0; w < 4; w++) __sincosf(0.5f * xw[w], &hs[w], &hc[w]);

    // product state magnitudes, (-1) of (-i)^popc folded in ((-i) itself is in U)
    float m[16];
    #pragma unroll
    for (int i = 0; i < 16; i++){
        float v = ((i&8)?hs[0]:hc[0]) * ((i&4)?hs[1]:hc[1]) * ((i&2)?hs[2]:hc[2]) * ((i&1)?hs[3]:hc[3]);
        m[i] = (__popc(i) & 2) ? -v : v;
    }

    // ---- both matvecs, packed f32x2 FMA (rows 4l..4l+3) ----
    unsigned long long pq[4], pv[4];
    #pragma unroll
    for (int r = 0; r < 4; r++){ pq[r] = 0ull; pv[r] = 0ull; }
    #pragma unroll
    for (int j = 0; j < 16; j++){
        unsigned long long mj2 = pk2(m[j], m[j]);
        float4 q0 = sUq[j*8 + 2*l], q1 = sUq[j*8 + 2*l + 1];
        float4 v0 = sUv[j*8 + 2*l], v1 = sUv[j*8 + 2*l + 1];
        pq[0] = fma2(pk2(q0.x,q0.y), mj2, pq[0]);
        pq[1] = fma2(pk2(q0.z,q0.w), mj2, pq[1]);
        pq[2] = fma2(pk2(q1.x,q1.y), mj2, pq[2]);
        pq[3] = fma2(pk2(q1.z,q1.w), mj2, pq[3]);
        pv[0] = fma2(pk2(v0.x,v0.y), mj2, pv[0]);
        pv[1] = fma2(pk2(v0.z,v0.w), mj2, pv[1]);
        pv[2] = fma2(pk2(v1.x,v1.y), mj2, pv[2]);
        pv[3] = fma2(pk2(v1.z,v1.w), mj2, pv[3]);
    }
    float2 stq[4], stv[4];
    #pragma unroll
    for (int r = 0; r < 4; r++){ stq[r] = upk2(pq[r]); stv[r] = upk2(pv[r]); }

    // ---- q path: RX(x) layer (symmetric pair update) ----
    #pragma unroll
    for (int w = 0; w < 2; w++){
        int d = 2 >> w;   // wire0: partner l^2, wire1: partner l^1
        float c = hc[w], s = hs[w];
        #pragma unroll
        for (int r = 0; r < 4; r++){
            float2 o = shflx(stq[r], d);
            stq[r] = make_float2(c*stq[r].x + s*o.y, c*stq[r].y - s*o.x);
        }
    }
    {   // wire2 (bit1): rows r <-> r^2
        float c = hc[2], s = hs[2];
        float2 n0 = make_float2(c*stq[0].x + s*stq[2].y, c*stq[0].y - s*stq[2].x);
        float2 n2 = make_float2(c*stq[2].x + s*stq[0].y, c*stq[2].y - s*stq[0].x);
        float2 n1 = make_float2(c*stq[1].x + s*stq[3].y, c*stq[1].y - s*stq[3].x);
        float2 n3 = make_float2(c*stq[3].x + s*stq[1].y, c*stq[3].y - s*stq[1].x);
        stq[0]=n0; stq[1]=n1; stq[2]=n2; stq[3]=n3;
    }
    {   // wire3 (bit0): rows r <-> r^1
        float c = hc[3], s = hs[3];
        float2 n0 = make_float2(c*stq[0].x + s*stq[1].y, c*stq[0].y - s*stq[1].x);
        float2 n1 = make_float2(c*stq[1].x + s*stq[0].y, c*stq[1].y - s*stq[0].x);
        float2 n2 = make_float2(c*stq[2].x + s*stq[3].y, c*stq[2].y - s*stq[3].x);
        float2 n3 = make_float2(c*stq[3].x + s*stq[2].y, c*stq[3].y - s*stq[2].x);
        stq[0]=n0; stq[1]=n1; stq[2]=n2; stq[3]=n3;
    }

    // ---- scores ----
    float n0 = stq[0].x*stq[0].x + stq[0].y*stq[0].y;
    float n1 = stq[1].x*stq[1].x + stq[1].y*stq[1].y;
    float n2 = stq[2].x*stq[2].x + stq[2].y*stq[2].y;
    float n3 = stq[3].x*stq[3].x + stq[3].y*stq[3].y;
    float nsum = n0 + n1 + n2 + n3;
    float z0 = (l & 2) ? -nsum : nsum;
    float z1 = (l & 1) ? -nsum : nsum;
    float z2 = n0 + n1 - n2 - n3;
    float z3 = n0 - n1 + n2 - n3;

    float x0 = 0.f, x1m = 0.f;
    #pragma unroll
    for (int r = 0; r < 4; r++){
        float2 o = shflx(stq[r], 2);
        x0 += stq[r].x*o.x + stq[r].y*o.y;
    }
    #pragma unroll
    for (int r = 0; r < 4; r++){
        float2 o = shflx(stq[r], 1);
        x1m += stq[r].x*o.x + stq[r].y*o.y;
    }
    float x2 = 2.f*(stq[0].x*stq[2].x + stq[0].y*stq[2].y + stq[1].x*stq[3].x + stq[1].y*stq[3].y);
    float x3 = 2.f*(stq[0].x*stq[1].x + stq[0].y*stq[1].y + stq[2].x*stq[3].x + stq[2].y*stq[3].y);

    #pragma unroll
    for (int d = 1; d <= 2; d <<= 1){
        z0 += __shfl_xor_sync(0xffffffffu, z0, d);
        z1 += __shfl_xor_sync(0xffffffffu, z1, d);
        z2 += __shfl_xor_sync(0xffffffffu, z2, d);
        z3 += __shfl_xor_sync(0xffffffffu, z3, d);
        x0 += __shfl_xor_sync(0xffffffffu, x0, d);
        x1m+= __shfl_xor_sync(0xffffffffu, x1m, d);
        x2 += __shfl_xor_sync(0xffffffffu, x2, d);
        x3 += __shfl_xor_sync(0xffffffffu, x3, d);
    }
    x0 *= sKx[0]; x1m *= sKx[1]; x2 *= sKx[2]; x3 *= sKx[3];

    float rz0 = fast_tanh(sqrtf(z0*z0 + x0*x0))   * (0.5f * PI_F);
    float rz1 = fast_tanh(sqrtf(z1*z1 + x1m*x1m)) * (0.5f * PI_F);
    float rz2 = fast_tanh(sqrtf(z2*z2 + x2*x2))   * (0.5f * PI_F);
    float rz3 = fast_tanh(sqrtf(z3*z3 + x3*x3))   * (0.5f * PI_F);

    // ---- v path: RZ phases ----
    float phl = ((l & 2) ? rz0 : -rz0) + ((l & 1) ? rz1 : -rz1);
    #pragma unroll
    for (int r = 0; r < 4; r++){
        float ph = phl + ((r & 2) ? rz2 : -rz2) + ((r & 1) ? rz3 : -rz3);
        float sp, cp; __sincosf(ph, &sp, &cp);
        stv[r] = make_float2(stv[r].x*cp - stv[r].y*sp, stv[r].x*sp + stv[r].y*cp);
    }
    // CNOT(0,1): lanes with bit l&2 take partner (l^1)'s value
    #pragma unroll
    for (int r = 0; r < 4; r++){
        float2 o = shflx(stv[r], 1);
        if (l & 2) stv[r] = o;
    }
    // CNOT(1,2): if (l&1): swap rows r <-> r^2
    if (l & 1){
        float2 tq = stv[0]; stv[0] = stv[2]; stv[2] = tq;
        tq = stv[1]; stv[1] = stv[3]; stv[3] = tq;
    }
    // CNOT(2,3): swap rows 2,3
    { float2 tq = stv[2]; stv[2] = stv[3]; stv[3] = tq; }

    // ---- final expectations ----
    float q0n = stv[0].x*stv[0].x + stv[0].y*stv[0].y;
    float q1n = stv[1].x*stv[1].x + stv[1].y*stv[1].y;
    float q2n = stv[2].x*stv[2].x + stv[2].y*stv[2].y;
    float q3n = stv[3].x*stv[3].x + stv[3].y*stv[3].y;
    float qs = q0n + q1n + q2n + q3n;
    float o0 = (l & 2) ? -qs : qs;
    float o1 = (l & 1) ? -qs : qs;
    float o2 = q0n + q1n - q2n - q3n;
    float o3 = q0n - q1n + q2n - q3n;

    float o4 = 0.f, o5 = 0.f;
    #pragma unroll
    for (int r = 0; r < 4; r++){
        float2 o = shflx(stv[r], 2);
        o4 += stv[r].x*o.x + stv[r].y*o.y;
    }
    #pragma unroll
    for (int r = 0; r < 4; r++){
        float2 o = shflx(stv[r], 1);
        o5 += stv[r].x*o.x + stv[r].y*o.y;
    }
    float o6 = 2.f*(stv[0].x*stv[2].x + stv[0].y*stv[2].y + stv[1].x*stv[3].x + stv[1].y*stv[3].y);
    float o7 = 2.f*(stv[0].x*stv[1].x + stv[0].y*stv[1].y + stv[2].x*stv[3].x + stv[2].y*stv[3].y);

    #pragma unroll
    for (int d = 1; d <= 2; d <<= 1){
        o0 += __shfl_xor_sync(0xffffffffu, o0, d);
        o1 += __shfl_xor_sync(0xffffffffu, o1, d);
        o2 += __shfl_xor_sync(0xffffffffu, o2, d);
        o3 += __shfl_xor_sync(0xffffffffu, o3, d);
        o4 += __shfl_xor_sync(0xffffffffu, o4, d);
        o5 += __shfl_xor_sync(0xffffffffu, o5, d);
        o6 += __shfl_xor_sync(0xffffffffu, o6, d);
        o7 += __shfl_xor_sync(0xffffffffu, o7, d);
    }

    if (l == 0){
        float o[8] = { o0, o1, o2, o3, o4, o5, o6, o7 };
        float mu = 0.f;
        #pragma unroll
        for (int k = 0; k < 8; k++) mu += o[k];
        mu *= 0.125f;
        float var = 0.f;
        #pragma unroll
        for (int k = 0; k < 8; k++){ float dd = o[k] - mu; var += dd * dd; }
        var *= 0.125f;
        float inv = rsqrtf(var + 1e-5f);

        float r0 = sHB[0], r1 = sHB[1];
        #pragma unroll
        for (int k = 0; k < 8; k++){
            float y = (o[k] - mu) * inv * sLnW[k] + sLnB[k];
            float g = 0.5f * y * (1.f + erff(y * 0.70710678118654752f));
            r0 += g * sHW[k];
            r1 += g * sHW[8 + k];
        }
        ((float2*)out)[s_idx] = make_float2(r0, r1);
    }
}

extern "C" void kernel_launch(void* const* d_in, const int* in_sizes, int n_in,
                              void* d_out, int out_size)
{
    const float* x1     = (const float*)d_in[0];
    const float* pre_w  = (const float*)d_in[1];
    const float* pre_b  = (const float*)d_in[2];
    const float* q_rot  = (const float*)d_in[3];
    const float* k_rot  = (const float*)d_in[4];
    const float* v_rot  = (const float*)d_in[5];
    const float* q_crx  = (const float*)d_in[6];
    const float* k_crx  = (const float*)d_in[7];
    const float* v_crx  = (const float*)d_in[8];
    const float* ln_w   = (const float*)d_in[9];
    const float* ln_b   = (const float*)d_in[10];
    const float* head_w = (const float*)d_in[11];
    const float* head_b = (const float*)d_in[12];

    int B = in_sizes[0] / 96;

    setup_kernel<<<17, 32>>>(q_rot, k_rot, v_rot, q_crx, k_crx, v_crx);
    qc_kernel<<<(B + 63) / 64, 256>>>(x1, pre_w, pre_b, ln_w, ln_b, head_w, head_b,
                                      (float*)d_out, B);
}